// round 16
// baseline (speedup 1.0000x reference)
#include <cuda_runtime.h>
#include <cuda_bf16.h>
#include <cstddef>
#include <cstdint>

typedef __nv_bfloat16 bf16;

#define NTHREADS 256
#define TROWS 64

// ======== pre-packed B-fragment image ========
// For each (segment, kb, nb, lane): uint4 = {reg0_hi, reg1_hi, reg0_lo, reg1_lo}
// reg0 = (w[k0],w[k0+1]), reg1 = (w[k0+8],w[k0+9]); k0 = kb*16+2*(lane%4), n = nb*8+lane/4.
__device__ __align__(16) uint4 g_wf[16384];

__constant__ int f_pre[10]  = {0,1024,2048,3072,4672,6272,7872,13056,15360,16384};
__constant__ int f_nout[9]  = {64,64,64,80,80,80,144,64,64};

__device__ __forceinline__ uint32_t pack_bf2(bf16 a, bf16 b) {
    return (uint32_t)__bfloat16_as_ushort(a) | ((uint32_t)__bfloat16_as_ushort(b) << 16);
}

__global__ void prep_kernel(const float* w0,const float* w1,const float* w2,
                            const float* w3,const float* w4,const float* w5,
                            const float* w6,const float* w7,const float* w8)
{
    const float* W[9] = {w0,w1,w2,w3,w4,w5,w6,w7,w8};
    int i = blockIdx.x * blockDim.x + threadIdx.x;
    if (i >= 16384) return;
    int s = 0;
    while (i >= f_pre[s + 1]) s++;
    int f = i - f_pre[s];
    int nout = f_nout[s];
    int nbc = nout >> 3;
    int kb = f / (nbc * 32);
    int r  = f - kb * nbc * 32;
    int nb = r >> 5, lane = r & 31;
    int n  = nb * 8 + (lane >> 2);
    int k0 = kb * 16 + (lane & 3) * 2;
    const float* Ws = W[s];
    float w00 = Ws[(k0)     * nout + n];
    float w01 = Ws[(k0 + 1) * nout + n];
    float w10 = Ws[(k0 + 8) * nout + n];
    float w11 = Ws[(k0 + 9) * nout + n];
    bf16 h00 = __float2bfloat16_rn(w00), h01 = __float2bfloat16_rn(w01);
    bf16 h10 = __float2bfloat16_rn(w10), h11 = __float2bfloat16_rn(w11);
    bf16 l00 = __float2bfloat16_rn(w00 - __bfloat162float(h00));
    bf16 l01 = __float2bfloat16_rn(w01 - __bfloat162float(h01));
    bf16 l10 = __float2bfloat16_rn(w10 - __bfloat162float(h10));
    bf16 l11 = __float2bfloat16_rn(w11 - __bfloat162float(h11));
    uint4 v;
    v.x = pack_bf2(h00, h01);
    v.y = pack_bf2(h10, h11);
    v.z = pack_bf2(l00, l01);
    v.w = pack_bf2(l10, l11);
    g_wf[i] = v;
}

// ======== helpers ========
__device__ __forceinline__ float lrelu(float v) { return v > 0.0f ? v : 0.01f * v; }
__device__ __forceinline__ uint32_t s2u(const void* p) {
    return (uint32_t)__cvta_generic_to_shared(p);
}
__device__ __forceinline__ void ldsm4(uint32_t a, uint32_t* r) {
    asm volatile("ldmatrix.sync.aligned.m8n8.x4.shared.b16 {%0,%1,%2,%3}, [%4];"
        : "=r"(r[0]), "=r"(r[1]), "=r"(r[2]), "=r"(r[3]) : "r"(a));
}
__device__ __forceinline__ void mma16816(float* d, const uint32_t* a, uint32_t b0, uint32_t b1) {
    asm volatile("mma.sync.aligned.m16n8k16.row.col.f32.bf16.bf16.f32 "
        "{%0,%1,%2,%3}, {%4,%5,%6,%7}, {%8,%9}, {%0,%1,%2,%3};"
        : "+f"(d[0]), "+f"(d[1]), "+f"(d[2]), "+f"(d[3])
        : "r"(a[0]), "r"(a[1]), "r"(a[2]), "r"(a[3]), "r"(b0), "r"(b1));
}

// ======== epilogue chunk maps ========
__constant__ int c_kind[31] = {0,0,0,0,0,0,0,0,0,0,0,0,1,1,1,1,0,0,0,1,0,0,0,0,0,1,1,1,1,1,1};
__constant__ int c_A[31]    = {320,152,304,304,304,304,304,152,152,152,152,152,
                               40,41,42,43, 152,208,416, 39, 208,152,416,360,152,
                               44,45,46,47,48,49};
__constant__ int c_B[31]    = {18,20,22,23,24,25,26,27,28,29,30,31,
                               0,2,3,5, 35,36,37, 1, 32,33,34,19,38,
                               4,4,4,4,4,4};
// blob: suit@0(40) rank@40(112) pos@152(56) action@208(96) active@304(16)
//       street@320(40) numpl@360(56) blind@416(16)

// ======== shared layout (bytes) ========
// fp32: blob 432f @0, sW 48f @432, sB 48f @480, bias 704f @528 -> 1232f = 4928B
#define B_P0H   4928
#define PLANEB  23552              /* 64 rows * 368B */
#define B_P0L   (B_P0H + PLANEB)
#define B_P1H   (B_P0L + PLANEB)
#define B_P1L   (B_P1H + PLANEB)
#define SMEM_BYTES (B_P1L + PLANEB)   /* 99136 -> 2 CTAs/SM */
#define PSTR    184                /* activation plane row stride in bf16 (368B, odd*16B) */

// split fp32 -> (hi, lo) bf16 pair-stores into both planes
__device__ __forceinline__ void split_store(bf16* H, bf16* Lp, int row, int k,
                                            float v0, float v1)
{
    bf16 h0 = __float2bfloat16_rn(v0), h1 = __float2bfloat16_rn(v1);
    bf16 l0 = __float2bfloat16_rn(v0 - __bfloat162float(h0));
    bf16 l1 = __float2bfloat16_rn(v1 - __bfloat162float(h1));
    *reinterpret_cast<uint32_t*>(H  + row * PSTR + k) = pack_bf2(h0, h1);
    *reinterpret_cast<uint32_t*>(Lp + row * PSTR + k) = pack_bf2(l0, l1);
}

// ======== one dense (sub-)layer: 3-pass bf16 split, warp owns M=32 (2 m-blocks) ========
// Computes n-pairs [PAIR0, PAIR0+NPS) of a segment whose full width is NOUTG.
// 8 warps = 2 m-groups (32 rows each) x 4 pair-groups. B frags reused across both m-blocks.
template<int NIN, int NOUTG, int PAIR0, int NPS, bool ACT, bool FINAL>
__device__ __forceinline__ void layer_mma(
    const bf16* __restrict__ srcH, const bf16* __restrict__ srcL,
    bf16* __restrict__ dstH, bf16* __restrict__ dstL,
    const uint4* __restrict__ wf,
    const float* __restrict__ bsm,
    float* __restrict__ out, size_t g0)
{
    const int t = threadIdx.x, L = t & 31, wid = t >> 5;
    const int mg = wid & 1, pg = wid >> 1;          // 2 m-groups x 4 pair-groups
    constexpr int NKB  = NIN / 16;
    constexpr int NBC  = NOUTG / 8;
    constexpr int MAXP = (NPS + 3) / 4;

    __syncthreads();   // previous layer's activations fully written

    float acc[MAXP][2][2][4];   // [pair][im][nb-in-pair][4]
    #pragma unroll
    for (int i = 0; i < MAXP; i++)
        #pragma unroll
        for (int m = 0; m < 2; m++)
            #pragma unroll
            for (int h = 0; h < 2; h++)
                #pragma unroll
                for (int q = 0; q < 4; q++) acc[i][m][h][q] = 0.0f;

    // A lane addressing (PTX x4 A-frag): row = mg*32 + im*16 + L%16, col8 = (L/16)*8
    const int arow = mg * 32 + (L & 15);
    const uint32_t uAH0 = s2u(srcH + arow * PSTR + ((L >> 4) << 3));
    const uint32_t uAL0 = s2u(srcL + arow * PSTR + ((L >> 4) << 3));
    constexpr uint32_t MOFS = 16 * PSTR * 2;   // +16 rows, bytes
    const uint4* wlane = wf + L;

    #pragma unroll
    for (int kb = 0; kb < NKB; kb++) {
        uint32_t ah0[4], al0[4], ah1[4], al1[4];
        ldsm4(uAH0 + kb * 32, ah0);
        ldsm4(uAH0 + MOFS + kb * 32, ah1);
        ldsm4(uAL0 + kb * 32, al0);
        ldsm4(uAL0 + MOFS + kb * 32, al1);
        #pragma unroll
        for (int i = 0; i < MAXP; i++) {
            int p = pg + 4 * i;
            if (p < NPS) {
                const uint4* fpq = wlane + (kb * NBC + 2 * (PAIR0 + p)) * 32;
                uint4 f0 = __ldg(fpq);
                uint4 f1 = __ldg(fpq + 32);
                mma16816(acc[i][0][0], ah0, f0.x, f0.y);
                mma16816(acc[i][0][1], ah0, f1.x, f1.y);
                mma16816(acc[i][1][0], ah1, f0.x, f0.y);
                mma16816(acc[i][1][1], ah1, f1.x, f1.y);
                mma16816(acc[i][0][0], ah0, f0.z, f0.w);
                mma16816(acc[i][0][1], ah0, f1.z, f1.w);
                mma16816(acc[i][1][0], ah1, f0.z, f0.w);
                mma16816(acc[i][1][1], ah1, f1.z, f1.w);
                mma16816(acc[i][0][0], al0, f0.x, f0.y);
                mma16816(acc[i][0][1], al0, f1.x, f1.y);
                mma16816(acc[i][1][0], al1, f0.x, f0.y);
                mma16816(acc[i][1][1], al1, f1.x, f1.y);
            }
        }
    }

    // epilogue: D frag (r0 = L/4, c0 = 2(L%4); rows r0, r0+8 per m-block)
    const int r0 = L >> 2, c0 = (L & 3) * 2;
    #pragma unroll
    for (int i = 0; i < MAXP; i++) {
        int p = pg + 4 * i;
        if (p < NPS) {
            #pragma unroll
            for (int m = 0; m < 2; m++) {
                const int gr0 = mg * 32 + m * 16 + r0, gr1 = gr0 + 8;
                #pragma unroll
                for (int h = 0; h < 2; h++) {
                    int n0 = (PAIR0 + p) * 16 + h * 8 + c0;
                    float b0 = bsm[n0], b1 = bsm[n0 + 1];
                    float v00 = acc[i][m][h][0] + b0, v01 = acc[i][m][h][1] + b1;
                    float v10 = acc[i][m][h][2] + b0, v11 = acc[i][m][h][3] + b1;
                    if (ACT) { v00 = lrelu(v00); v01 = lrelu(v01); v10 = lrelu(v10); v11 = lrelu(v11); }
                    if (FINAL) {
                        *reinterpret_cast<float2*>(out + (g0 + gr0) * 312 + n0) = make_float2(v00, v01);
                        *reinterpret_cast<float2*>(out + (g0 + gr1) * 312 + n0) = make_float2(v10, v11);
                    } else {
                        split_store(dstH, dstL, gr0, n0, v00, v01);
                        split_store(dstH, dstL, gr1, n0, v10, v11);
                    }
                }
            }
        }
    }
}

__global__ void __launch_bounds__(NTHREADS, 2)
preproc_kernel(const float* __restrict__ state,
               const float* __restrict__ suit_emb, const float* __restrict__ rank_emb,
               const float* __restrict__ hb1, const float* __restrict__ hb2,
               const float* __restrict__ hb3, const float* __restrict__ bb1,
               const float* __restrict__ bb2, const float* __restrict__ bb3,
               const float* __restrict__ cb1, const float* __restrict__ cb2,
               const float* __restrict__ cb3,
               const float* __restrict__ pos_emb, const float* __restrict__ action_emb,
               const float* __restrict__ active_emb, const float* __restrict__ street_emb,
               const float* __restrict__ numpl_emb, const float* __restrict__ blind_emb,
               const float* __restrict__ scalar_W, const float* __restrict__ scalar_b,
               float* __restrict__ out)
{
    extern __shared__ __align__(16) char smem[];
    float* fp   = reinterpret_cast<float*>(smem);
    float* blob = fp;
    float* sW   = fp + 432;
    float* sB   = fp + 480;
    float* bias = fp + 528;
    bf16* P0H = reinterpret_cast<bf16*>(smem + B_P0H);
    bf16* P0L = reinterpret_cast<bf16*>(smem + B_P0L);
    bf16* P1H = reinterpret_cast<bf16*>(smem + B_P1H);
    bf16* P1L = reinterpret_cast<bf16*>(smem + B_P1L);

    const int t = threadIdx.x;
    const size_t g0 = (size_t)blockIdx.x * TROWS;
    const float* st = state + g0 * 50;

    // ---- stage tables + biases ----
    for (int i = t; i < 40;  i += NTHREADS) blob[0   + i] = suit_emb[i];
    for (int i = t; i < 112; i += NTHREADS) blob[40  + i] = rank_emb[i];
    for (int i = t; i < 56;  i += NTHREADS) blob[152 + i] = pos_emb[i];
    for (int i = t; i < 96;  i += NTHREADS) blob[208 + i] = action_emb[i];
    for (int i = t; i < 16;  i += NTHREADS) blob[304 + i] = active_emb[i];
    for (int i = t; i < 40;  i += NTHREADS) blob[320 + i] = street_emb[i];
    for (int i = t; i < 56;  i += NTHREADS) blob[360 + i] = numpl_emb[i];
    for (int i = t; i < 16;  i += NTHREADS) blob[416 + i] = blind_emb[i];
    for (int i = t; i < 48;  i += NTHREADS) { sW[i] = scalar_W[i]; sB[i] = scalar_b[i]; }
    for (int i = t; i < 64;  i += NTHREADS) bias[0   + i] = hb1[i];
    for (int i = t; i < 64;  i += NTHREADS) bias[64  + i] = hb2[i];
    for (int i = t; i < 64;  i += NTHREADS) bias[128 + i] = hb3[i];
    for (int i = t; i < 80;  i += NTHREADS) bias[192 + i] = bb1[i];
    for (int i = t; i < 80;  i += NTHREADS) bias[272 + i] = bb2[i];
    for (int i = t; i < 80;  i += NTHREADS) bias[352 + i] = bb3[i];
    for (int i = t; i < 144; i += NTHREADS) bias[432 + i] = cb1[i];
    for (int i = t; i < 64;  i += NTHREADS) bias[576 + i] = cb2[i];
    for (int i = t; i < 64;  i += NTHREADS) bias[640 + i] = cb3[i];
    __syncthreads();

    const float4* blob4 = reinterpret_cast<const float4*>(blob);

    // ---- cheap output columns 64..311: coalesced float4 stores ----
    for (int i = t; i < TROWS * 62; i += NTHREADS) {
        int r = i / 62, q = i - r * 62;
        int ch = q >> 1, half = q & 1;
        int kind = c_kind[ch], Ai = c_A[ch], Bc = c_B[ch];
        float4 v;
        if (kind == 0) {
            int xi = (int)__ldg(st + r * 50 + Bc);
            v = blob4[(Ai >> 2) + xi * 2 + half];
        } else {
            float s = __ldg(st + r * 50 + Ai);
            float4 w = *reinterpret_cast<const float4*>(sW + Bc * 8 + half * 4);
            float4 p = *reinterpret_cast<const float4*>(sB + Bc * 8 + half * 4);
            v = make_float4(s * w.x + p.x, s * w.y + p.y, s * w.z + p.z, s * w.w + p.w);
        }
        *reinterpret_cast<float4*>(out + (g0 + r) * 312 + 64 + q * 4) = v;
    }

    // ---- gather hand input (64 rows x 4 cards x 16 feats) -> P0 planes ----
    {
        int r = t >> 2, c = t & 3;   // 256 threads = 64 rows x 4 cards
        int s  = (int)__ldg(st + r * 50 + 2 * c + 1);
        int rk = (int)__ldg(st + r * 50 + 2 * c);
        float v[16];
        *reinterpret_cast<float4*>(v)      = blob4[s * 2];
        *reinterpret_cast<float4*>(v + 4)  = blob4[s * 2 + 1];
        *reinterpret_cast<float4*>(v + 8)  = blob4[10 + rk * 2];
        *reinterpret_cast<float4*>(v + 12) = blob4[10 + rk * 2 + 1];
        #pragma unroll
        for (int p = 0; p < 8; p++)
            split_store(P0H, P0L, r, c * 16 + 2 * p, v[2 * p], v[2 * p + 1]);
    }
    // (h1's entry barrier establishes visibility)

    layer_mma<64, 64, 0, 4, true,  false>(P0H, P0L, P1H, P1L, g_wf + 0,    bias + 0,   out, g0);
    layer_mma<64, 64, 0, 4, true,  false>(P1H, P1L, P0H, P0L, g_wf + 1024, bias + 64,  out, g0);
    layer_mma<64, 64, 0, 4, false, false>(P0H, P0L, P1H, P1L, g_wf + 2048, bias + 128, out, g0);
    // hand output in P1[0:64)

    __syncthreads();  // h3 warps done reading P0 before board gather overwrites
    for (int i = t; i < TROWS * 8; i += NTHREADS) {
        int r = i >> 3, c = i & 7;
        if (c < 5) {
            int s  = (int)__ldg(st + r * 50 + 9 + 2 * c);
            int rk = (int)__ldg(st + r * 50 + 8 + 2 * c);
            float v[16];
            *reinterpret_cast<float4*>(v)      = blob4[s * 2];
            *reinterpret_cast<float4*>(v + 4)  = blob4[s * 2 + 1];
            *reinterpret_cast<float4*>(v + 8)  = blob4[10 + rk * 2];
            *reinterpret_cast<float4*>(v + 12) = blob4[10 + rk * 2 + 1];
            #pragma unroll
            for (int p = 0; p < 8; p++)
                split_store(P0H, P0L, r, c * 16 + 2 * p, v[2 * p], v[2 * p + 1]);
        }
    }

    layer_mma<80, 80, 0, 5, true,  false>(P0H, P0L, P1H + 64, P1L + 64, g_wf + 3072, bias + 192, out, g0);
    layer_mma<80, 80, 0, 5, true,  false>(P1H + 64, P1L + 64, P0H, P0L, g_wf + 4672, bias + 272, out, g0);
    layer_mma<80, 80, 0, 5, false, false>(P0H, P0L, P1H + 64, P1L + 64, g_wf + 6272, bias + 352, out, g0);
    // P1 holds concat[hand(0:64), board(64:144)]

    // c1 split into two n-slices (pairs 0..4, then 5..8) to keep MAXP<=2
    layer_mma<144, 144, 0, 5, true, false>(P1H, P1L, P0H, P0L, g_wf + 7872, bias + 432, out, g0);
    layer_mma<144, 144, 5, 4, true, false>(P1H, P1L, P0H, P0L, g_wf + 7872, bias + 432, out, g0);
    layer_mma<144, 64,  0, 4, true, false>(P0H, P0L, P1H, P1L, g_wf + 13056, bias + 576, out, g0);
    layer_mma<64,  64,  0, 4, false, true>(P1H, P1L, P0H, P0L, g_wf + 15360, bias + 640, out, g0);
}

extern "C" void kernel_launch(void* const* d_in, const int* in_sizes, int n_in,
                              void* d_out, int out_size)
{
    (void)n_in; (void)out_size;
    cudaFuncSetAttribute(preproc_kernel, cudaFuncAttributeMaxDynamicSharedMemorySize, SMEM_BYTES);

    // one-time-per-graph fragment packing (bf16 hi/lo split, mma-lane layout)
    prep_kernel<<<64, 256>>>(
        (const float*)d_in[3],  (const float*)d_in[5],  (const float*)d_in[7],
        (const float*)d_in[9],  (const float*)d_in[11], (const float*)d_in[13],
        (const float*)d_in[15], (const float*)d_in[17], (const float*)d_in[19]);

    const int nrows = in_sizes[0] / 50;     // 262144
    const int grid  = nrows / TROWS;        // 4096

    preproc_kernel<<<grid, NTHREADS, SMEM_BYTES>>>(
        (const float*)d_in[0],
        (const float*)d_in[1],  (const float*)d_in[2],
        (const float*)d_in[4],  (const float*)d_in[6],  (const float*)d_in[8],
        (const float*)d_in[10], (const float*)d_in[12], (const float*)d_in[14],
        (const float*)d_in[16], (const float*)d_in[18], (const float*)d_in[20],
        (const float*)d_in[21], (const float*)d_in[22],
        (const float*)d_in[23], (const float*)d_in[24],
        (const float*)d_in[25], (const float*)d_in[26],
        (const float*)d_in[27], (const float*)d_in[28],
        (float*)d_out);
}